// round 1
// baseline (speedup 1.0000x reference)
#include <cuda_runtime.h>
#include <cstddef>

#define S_LEN 2048
#define BATCH 4
#define DIM   1024
#define MQKV  (BATCH * S_LEN)   // 8192

// ---- scratch (static device globals; no allocation in kernel_launch) ----
__device__ float g_xf[(size_t)MQKV * DIM];          // x transposed to (B,S,D)
__device__ float g_q [(size_t)MQKV * DIM];
__device__ float g_k [(size_t)MQKV * DIM];
__device__ float g_v [(size_t)MQKV * DIM];
__device__ float g_sc[(size_t)BATCH * S_LEN * S_LEN]; // scores / attn probs

// ---------------------------------------------------------------------------
// transpose: xf[(b*S+s)*D + d] = x[(s*B+b)*D + d]
// grid = B*S blocks, 256 threads, one float4 per thread (D/4 = 256)
// ---------------------------------------------------------------------------
__global__ __launch_bounds__(256) void transpose_x(const float* __restrict__ x,
                                                   float* __restrict__ xf) {
    int bs = blockIdx.x;
    int b = bs / S_LEN, s = bs % S_LEN;
    const float4* src = (const float4*)(x + ((size_t)s * BATCH + b) * DIM);
    float4* dst = (float4*)(xf + (size_t)bs * DIM);
    dst[threadIdx.x] = src[threadIdx.x];
}

// ---------------------------------------------------------------------------
// NT GEMM: C[m,n] = alpha * sum_k A[m,k] * Bw[n,k] (+ bias[n])
// A: M x K row-major, Bw: N x K row-major (both K-contiguous).
// Tile 128x128x16, 256 threads, 8x8 microtile. Batched via blockIdx.z strides.
// ---------------------------------------------------------------------------
__global__ __launch_bounds__(256, 2)
void gemm_nt(const float* __restrict__ A, const float* __restrict__ Bw,
             const float* __restrict__ bias, float* __restrict__ C,
             int M, int N, int K, float alpha,
             size_t sA, size_t sB, size_t sC)
{
    A  += sA * (size_t)blockIdx.z;
    Bw += sB * (size_t)blockIdx.z;
    C  += sC * (size_t)blockIdx.z;

    const int m0 = blockIdx.y * 128;
    const int n0 = blockIdx.x * 128;

    __shared__ float As[16][132];   // padded to dodge transpose-store conflicts
    __shared__ float Bs[16][132];

    const int tid = threadIdx.x;
    const int tx = tid & 15, ty = tid >> 4;
    const int lr = tid >> 2;          // 0..63
    const int lc = (tid & 3) << 2;    // 0,4,8,12

    float acc[8][8];
    #pragma unroll
    for (int i = 0; i < 8; ++i)
        #pragma unroll
        for (int j = 0; j < 8; ++j) acc[i][j] = 0.f;

    for (int k0 = 0; k0 < K; k0 += 16) {
        #pragma unroll
        for (int h = 0; h < 2; ++h) {
            int r = lr + h * 64;
            float4 va = *(const float4*)(A  + (size_t)(m0 + r) * K + k0 + lc);
            As[lc+0][r] = va.x; As[lc+1][r] = va.y;
            As[lc+2][r] = va.z; As[lc+3][r] = va.w;
            float4 vb = *(const float4*)(Bw + (size_t)(n0 + r) * K + k0 + lc);
            Bs[lc+0][r] = vb.x; Bs[lc+1][r] = vb.y;
            Bs[lc+2][r] = vb.z; Bs[lc+3][r] = vb.w;
        }
        __syncthreads();
        #pragma unroll
        for (int kk = 0; kk < 16; ++kk) {
            float a[8], b[8];
            *(float4*)&a[0] = *(const float4*)&As[kk][ty * 8];
            *(float4*)&a[4] = *(const float4*)&As[kk][ty * 8 + 4];
            *(float4*)&b[0] = *(const float4*)&Bs[kk][tx * 8];
            *(float4*)&b[4] = *(const float4*)&Bs[kk][tx * 8 + 4];
            #pragma unroll
            for (int i = 0; i < 8; ++i)
                #pragma unroll
                for (int j = 0; j < 8; ++j)
                    acc[i][j] = fmaf(a[i], b[j], acc[i][j]);
        }
        __syncthreads();
    }

    #pragma unroll
    for (int i = 0; i < 8; ++i) {
        int row = m0 + ty * 8 + i;
        #pragma unroll
        for (int j = 0; j < 8; j += 4) {
            int col = n0 + tx * 8 + j;
            float4 o;
            o.x = alpha * acc[i][j+0];
            o.y = alpha * acc[i][j+1];
            o.z = alpha * acc[i][j+2];
            o.w = alpha * acc[i][j+3];
            if (bias) {
                float4 bb = *(const float4*)(bias + col);
                o.x += bb.x; o.y += bb.y; o.z += bb.z; o.w += bb.w;
            }
            *(float4*)(C + (size_t)row * N + col) = o;
        }
    }
}

// ---------------------------------------------------------------------------
// NN GEMM: C[m,n] = sum_k A[m,k] * Bw[k,n]
// A: M x K row-major, Bw: K x N row-major. Same tiling as gemm_nt.
// ---------------------------------------------------------------------------
__global__ __launch_bounds__(256, 2)
void gemm_nn(const float* __restrict__ A, const float* __restrict__ Bw,
             float* __restrict__ C,
             int M, int N, int K,
             size_t sA, size_t sB, size_t sC)
{
    A  += sA * (size_t)blockIdx.z;
    Bw += sB * (size_t)blockIdx.z;
    C  += sC * (size_t)blockIdx.z;

    const int m0 = blockIdx.y * 128;
    const int n0 = blockIdx.x * 128;

    __shared__ float As[16][132];
    __shared__ float Bs[16][132];

    const int tid = threadIdx.x;
    const int tx = tid & 15, ty = tid >> 4;
    const int lr = tid >> 2;          // A loader: 0..63
    const int lc = (tid & 3) << 2;
    const int kb = tid >> 5;          // B loader: 0..7
    const int nb = (tid & 31) << 2;   // 0..124

    float acc[8][8];
    #pragma unroll
    for (int i = 0; i < 8; ++i)
        #pragma unroll
        for (int j = 0; j < 8; ++j) acc[i][j] = 0.f;

    for (int k0 = 0; k0 < K; k0 += 16) {
        #pragma unroll
        for (int h = 0; h < 2; ++h) {
            int r = lr + h * 64;
            float4 va = *(const float4*)(A + (size_t)(m0 + r) * K + k0 + lc);
            As[lc+0][r] = va.x; As[lc+1][r] = va.y;
            As[lc+2][r] = va.z; As[lc+3][r] = va.w;
            int kk2 = kb + h * 8;
            float4 vb = *(const float4*)(Bw + (size_t)(k0 + kk2) * N + n0 + nb);
            *(float4*)&Bs[kk2][nb] = vb;
        }
        __syncthreads();
        #pragma unroll
        for (int kk = 0; kk < 16; ++kk) {
            float a[8], b[8];
            *(float4*)&a[0] = *(const float4*)&As[kk][ty * 8];
            *(float4*)&a[4] = *(const float4*)&As[kk][ty * 8 + 4];
            *(float4*)&b[0] = *(const float4*)&Bs[kk][tx * 8];
            *(float4*)&b[4] = *(const float4*)&Bs[kk][tx * 8 + 4];
            #pragma unroll
            for (int i = 0; i < 8; ++i)
                #pragma unroll
                for (int j = 0; j < 8; ++j)
                    acc[i][j] = fmaf(a[i], b[j], acc[i][j]);
        }
        __syncthreads();
    }

    #pragma unroll
    for (int i = 0; i < 8; ++i) {
        int row = m0 + ty * 8 + i;
        #pragma unroll
        for (int j = 0; j < 8; j += 4) {
            int col = n0 + tx * 8 + j;
            float4 o;
            o.x = acc[i][j+0]; o.y = acc[i][j+1];
            o.z = acc[i][j+2]; o.w = acc[i][j+3];
            *(float4*)(C + (size_t)row * N + col) = o;
        }
    }
}

// ---------------------------------------------------------------------------
// softmax over rows of g_sc (each row = S_LEN floats), in place.
// grid = BATCH*S_LEN rows, 256 threads.
// ---------------------------------------------------------------------------
__global__ __launch_bounds__(256) void softmax_rows(float* __restrict__ sc) {
    float4* p4 = (float4*)(sc + (size_t)blockIdx.x * S_LEN);
    const int tid = threadIdx.x;
    __shared__ float red[8];

    float lmax = -1e30f;
    #pragma unroll
    for (int i = tid; i < S_LEN / 4; i += 256) {
        float4 v = p4[i];
        lmax = fmaxf(lmax, fmaxf(fmaxf(v.x, v.y), fmaxf(v.z, v.w)));
    }
    #pragma unroll
    for (int o = 16; o; o >>= 1) lmax = fmaxf(lmax, __shfl_xor_sync(~0u, lmax, o));
    if ((tid & 31) == 0) red[tid >> 5] = lmax;
    __syncthreads();
    float gmax = red[0];
    #pragma unroll
    for (int w = 1; w < 8; ++w) gmax = fmaxf(gmax, red[w]);
    __syncthreads();

    float lsum = 0.f;
    #pragma unroll
    for (int i = tid; i < S_LEN / 4; i += 256) {
        float4 v = p4[i];
        v.x = __expf(v.x - gmax); v.y = __expf(v.y - gmax);
        v.z = __expf(v.z - gmax); v.w = __expf(v.w - gmax);
        lsum += (v.x + v.y) + (v.z + v.w);
        p4[i] = v;
    }
    #pragma unroll
    for (int o = 16; o; o >>= 1) lsum += __shfl_xor_sync(~0u, lsum, o);
    if ((tid & 31) == 0) red[tid >> 5] = lsum;
    __syncthreads();
    float gsum = 0.f;
    #pragma unroll
    for (int w = 0; w < 8; ++w) gsum += red[w];
    float inv = 1.f / gsum;

    #pragma unroll
    for (int i = tid; i < S_LEN / 4; i += 256) {
        float4 v = p4[i];
        v.x *= inv; v.y *= inv; v.z *= inv; v.w *= inv;
        p4[i] = v;
    }
}

// ---------------------------------------------------------------------------
extern "C" void kernel_launch(void* const* d_in, const int* in_sizes, int n_in,
                              void* d_out, int out_size) {
    const float* x  = (const float*)d_in[0];
    const float* Wq = (const float*)d_in[1];
    const float* bq = (const float*)d_in[2];
    const float* Wk = (const float*)d_in[3];
    const float* bk = (const float*)d_in[4];
    const float* Wv = (const float*)d_in[5];
    const float* bv = (const float*)d_in[6];
    float* out = (float*)d_out;

    float *xf, *q, *k, *v, *sc;
    cudaGetSymbolAddress((void**)&xf, g_xf);
    cudaGetSymbolAddress((void**)&q,  g_q);
    cudaGetSymbolAddress((void**)&k,  g_k);
    cudaGetSymbolAddress((void**)&v,  g_v);
    cudaGetSymbolAddress((void**)&sc, g_sc);

    // 1) x (S,B,D) -> xf (B,S,D)
    transpose_x<<<MQKV, 256>>>(x, xf);

    // 2) QKV projections: (8192x1024) @ (1024x1024)^T + bias
    {
        dim3 grid(DIM / 128, MQKV / 128, 1);
        gemm_nt<<<grid, 256>>>(xf, Wq, bq, q, MQKV, DIM, DIM, 1.f, 0, 0, 0);
        gemm_nt<<<grid, 256>>>(xf, Wk, bk, k, MQKV, DIM, DIM, 1.f, 0, 0, 0);
        gemm_nt<<<grid, 256>>>(xf, Wv, bv, v, MQKV, DIM, DIM, 1.f, 0, 0, 0);
    }

    // 3) scores = (Q K^T) / sqrt(D), batched over B
    {
        dim3 grid(S_LEN / 128, S_LEN / 128, BATCH);
        gemm_nt<<<grid, 256>>>(q, k, nullptr, sc,
                               S_LEN, S_LEN, DIM, 0.03125f,
                               (size_t)S_LEN * DIM, (size_t)S_LEN * DIM,
                               (size_t)S_LEN * S_LEN);
    }

    // 4) softmax over last dim, in place
    softmax_rows<<<BATCH * S_LEN, 256>>>(sc);

    // 5) out = P @ V, batched over B; writes d_out directly ((B,S,D) flat ==
    //    reshape(weighted, x.shape))
    {
        dim3 grid(DIM / 128, S_LEN / 128, BATCH);
        gemm_nn<<<grid, 256>>>(sc, v, out,
                               S_LEN, DIM, S_LEN,
                               (size_t)S_LEN * S_LEN, (size_t)S_LEN * DIM,
                               (size_t)S_LEN * DIM);
    }
}